// round 3
// baseline (speedup 1.0000x reference)
#include <cuda_runtime.h>
#include <cuda_bf16.h>

#define NBX 512
#define NBY 512
#define KK  5
#define BINF 1.0f
#define TARGET_AREA 0.9f
#define NC (NBX * NBY)          // 262144 cells (sx0,sy0 both <= 507)
#define CAP 16                  // bucket capacity per cell
#define OVF_CAP (1 << 20)

// ---- static device scratch (no runtime allocation allowed) ----
__device__ __align__(16) float g_density[NC];          // 1 MB
__device__ int    g_cnt[NC];                           // 1 MB
__device__ float4 g_rec[CAP * NC];                     // 64 MB, slot-major
__device__ float4 g_ovf[OVF_CAP];                      // 16 MB
__device__ int    g_ovf_cnt;

// Vectorized fp32 reduction (no return) — sm_90+
__device__ __forceinline__ void red_add_v4(float* addr, float a, float b, float c, float d) {
    asm volatile("red.global.add.v4.f32 [%0], {%1, %2, %3, %4};"
                 :: "l"(addr), "f"(a), "f"(b), "f"(c), "f"(d) : "memory");
}

// 1D potentials for the 5-bin window starting at s0 (x flavor, 5 values)
__device__ __forceinline__ void pot_x5(float coord, float s, int s0, float* p) {
    float ctr = coord + 0.5f * s;
    float a = 4.0f / ((s + 2.0f) * (s + 4.0f));
    float c = s;
    float cb = c * (2.0f / (s + 4.0f));
    float p1 = 0.5f * s + 1.0f;
    float p2 = 0.5f * s + 2.0f;
#pragma unroll
    for (int k = 0; k < KK; k++) {
        float d = fabsf(ctr - ((float)(s0 + k) + 0.5f));
        float v;
        if (d < p1)      v = c * (1.0f - a * d * d);
        else if (d < p2) { float t = d - p2; v = cb * t * t; }
        else             v = 0.0f;
        p[k] = v;
    }
}

// y flavor: 8 padded lanes from aligned ybase, masked to [sy0, sy0+5)
__device__ __forceinline__ void pot_y8(float coord, float s, int sy0, int ybase, float* p) {
    float ctr = coord + 0.5f * s;
    float a = 4.0f / ((s + 2.0f) * (s + 4.0f));
    float c = s;
    float cb = c * (2.0f / (s + 4.0f));
    float p1 = 0.5f * s + 1.0f;
    float p2 = 0.5f * s + 2.0f;
#pragma unroll
    for (int j = 0; j < 8; j++) {
        int g = ybase + j;
        float d = fabsf(ctr - ((float)g + 0.5f));
        float v;
        if (d < p1)      v = c * (1.0f - a * d * d);
        else if (d < p2) { float t = d - p2; v = cb * t * t; }
        else             v = 0.0f;
        bool in = (g >= sy0) && (g < sy0 + KK);
        p[j] = in ? v : 0.0f;
    }
}

// ---------------------------------------------------------------------------
// Kernel 1: init map, counters, output scalar
// ---------------------------------------------------------------------------
__global__ void init_kernel(const float* __restrict__ initial, float* __restrict__ out) {
    int i = blockIdx.x * blockDim.x + threadIdx.x;
    if (i < NC) {
        g_density[i] = initial[i];
        g_cnt[i] = 0;
    }
    if (i == 0) { out[0] = 0.0f; g_ovf_cnt = 0; }
}

// ---------------------------------------------------------------------------
// Kernel 2: bucket nodes by exact (sx0, sy0) cell; 16B record per node
// ---------------------------------------------------------------------------
__global__ void __launch_bounds__(256) bucket_kernel(
    const float* __restrict__ pos,
    const float* __restrict__ sxs,
    const float* __restrict__ sys,
    int n)
{
    int i = blockIdx.x * blockDim.x + threadIdx.x;
    if (i >= n) return;
    float x  = pos[i];
    float y  = pos[n + i];
    float sx = sxs[i];
    float sy = sys[i];

    int sx0 = min(max((int)floorf(x - 2.0f), 0), NBX - KK);
    int sy0 = min(max((int)floorf(y - 2.0f), 0), NBY - KK);
    int c = sx0 * NBY + sy0;

    int slot = atomicAdd(&g_cnt[c], 1);
    float4 r = make_float4(x, y, sx, sy);
    if (slot < CAP) {
        g_rec[slot * NC + c] = r;
    } else {
        int o = atomicAdd(&g_ovf_cnt, 1);
        if (o < OVF_CAP) g_ovf[o] = r;
    }
}

// ---------------------------------------------------------------------------
// Kernel 3: one thread per cell — merge stamps in registers, deposit once
// ---------------------------------------------------------------------------
__global__ void __launch_bounds__(256) merge_kernel() {
    int c = blockIdx.x * blockDim.x + threadIdx.x;
    if (c >= NC) return;
    int cnt = min(g_cnt[c], CAP);
    if (cnt == 0) return;

    int sx0 = c / NBY;
    int sy0 = c % NBY;
    int ybase = sy0 & ~3;

    float st[KK][8];
#pragma unroll
    for (int kx = 0; kx < KK; kx++)
#pragma unroll
        for (int j = 0; j < 8; j++) st[kx][j] = 0.0f;

    for (int s = 0; s < cnt; s++) {
        float4 r = g_rec[s * NC + c];
        float px[KK], py[8];
        pot_x5(r.x, r.z, sx0, px);
        pot_y8(r.y, r.w, sy0, ybase, py);
#pragma unroll
        for (int kx = 0; kx < KK; kx++) {
            float vx = px[kx];
#pragma unroll
            for (int j = 0; j < 8; j++) st[kx][j] += vx * py[j];
        }
    }

    float* base = &g_density[sx0 * NBY + ybase];
#pragma unroll
    for (int kx = 0; kx < KK; kx++) {
        float* b = base + kx * NBY;
        if (st[kx][0] != 0.0f || st[kx][1] != 0.0f || st[kx][2] != 0.0f || st[kx][3] != 0.0f)
            red_add_v4(b, st[kx][0], st[kx][1], st[kx][2], st[kx][3]);
        if (st[kx][4] != 0.0f || st[kx][5] != 0.0f || st[kx][6] != 0.0f || st[kx][7] != 0.0f)
            red_add_v4(b + 4, st[kx][4], st[kx][5], st[kx][6], st[kx][7]);
    }
}

// ---------------------------------------------------------------------------
// Kernel 4: overflow nodes (unsorted, per-node scatter)
// ---------------------------------------------------------------------------
__global__ void __launch_bounds__(256) overflow_kernel() {
    int total = min(g_ovf_cnt, OVF_CAP);
    for (int i = blockIdx.x * blockDim.x + threadIdx.x; i < total;
         i += gridDim.x * blockDim.x) {
        float4 r = g_ovf[i];
        int sx0 = min(max((int)floorf(r.x - 2.0f), 0), NBX - KK);
        int sy0 = min(max((int)floorf(r.y - 2.0f), 0), NBY - KK);
        int ybase = sy0 & ~3;
        float px[KK], py[8];
        pot_x5(r.x, r.z, sx0, px);
        pot_y8(r.y, r.w, sy0, ybase, py);
        float* base = &g_density[sx0 * NBY + ybase];
#pragma unroll
        for (int kx = 0; kx < KK; kx++) {
            float vx = px[kx];
            if (vx != 0.0f) {
                float* b = base + kx * NBY;
                float q0 = vx * py[0], q1 = vx * py[1], q2 = vx * py[2], q3 = vx * py[3];
                float q4 = vx * py[4], q5 = vx * py[5], q6 = vx * py[6], q7 = vx * py[7];
                if (q0 != 0.0f || q1 != 0.0f || q2 != 0.0f || q3 != 0.0f)
                    red_add_v4(b, q0, q1, q2, q3);
                if (q4 != 0.0f || q5 != 0.0f || q6 != 0.0f || q7 != 0.0f)
                    red_add_v4(b + 4, q4, q5, q6, q7);
            }
        }
    }
}

// ---------------------------------------------------------------------------
// Kernel 5: cost = sum((density - target)^2)
// ---------------------------------------------------------------------------
__global__ void __launch_bounds__(256) reduce_kernel(float* __restrict__ out) {
    __shared__ float sdata[8];
    int tid = threadIdx.x;
    float acc = 0.0f;
    for (int i = blockIdx.x * blockDim.x + tid; i < NC;
         i += gridDim.x * blockDim.x) {
        float d = g_density[i] - TARGET_AREA;
        acc += d * d;
    }
#pragma unroll
    for (int off = 16; off > 0; off >>= 1)
        acc += __shfl_xor_sync(0xFFFFFFFF, acc, off);
    if ((tid & 31) == 0) sdata[tid >> 5] = acc;
    __syncthreads();
    if (tid < 8) {
        float v = sdata[tid];
#pragma unroll
        for (int off = 4; off > 0; off >>= 1)
            v += __shfl_xor_sync(0xFF, v, off);
        if (tid == 0) atomicAdd(out, v);
    }
}

// ---------------------------------------------------------------------------
extern "C" void kernel_launch(void* const* d_in, const int* in_sizes, int n_in,
                              void* d_out, int out_size) {
    const float* pos = (const float*)d_in[0];
    const float* sx  = (const float*)d_in[1];
    const float* sy  = (const float*)d_in[2];
    // d_in[3..8]: ax,bx,cx,ay,by,cy — recomputed analytically from sx/sy
    // d_in[9], d_in[10]: bin centers — analytic
    const float* initial = (const float*)d_in[11];
    float* out = (float*)d_out;

    int n = in_sizes[1];

    init_kernel<<<(NC + 255) / 256, 256>>>(initial, out);
    bucket_kernel<<<(n + 255) / 256, 256>>>(pos, sx, sy, n);
    merge_kernel<<<(NC + 255) / 256, 256>>>();
    overflow_kernel<<<256, 256>>>();
    reduce_kernel<<<256, 256>>>(out);
}

// round 4
// speedup vs baseline: 1.0816x; 1.0816x over previous
#include <cuda_runtime.h>
#include <cuda_bf16.h>

#define NBX 512
#define NBY 512
#define KK  5
#define TARGET_AREA 0.9f
#define NC (NBX * NBY)          // 262144 (bucket key space: 511x511 used, stride 512)
#define CAP 16                  // bucket capacity per cell (P(>16 | lambda~3.9) ~ 3e-7)
#define OVF_CAP (1 << 18)

// ---- static device scratch (no runtime allocation allowed) ----
__device__ __align__(16) float g_density[NC];          // 1 MB
__device__ int    g_cnt[NC];                           // 1 MB
__device__ float4 g_rec[CAP * NC];                     // 64 MB, slot-major
__device__ float4 g_ovf[OVF_CAP];                      // 4 MB (safety net)
__device__ int    g_ovf_cnt;

// Vectorized fp32 reduction (no return) — sm_90+
__device__ __forceinline__ void red_add_v4(float* addr, float a, float b, float c, float d) {
    asm volatile("red.global.add.v4.f32 [%0], {%1, %2, %3, %4};"
                 :: "l"(addr), "f"(a), "f"(b), "f"(c), "f"(d) : "memory");
}

// x flavor: 5 window potentials starting at s0
__device__ __forceinline__ void pot_x5(float coord, float s, int s0, float* p) {
    float ctr = coord + 0.5f * s;
    float a = 4.0f / ((s + 2.0f) * (s + 4.0f));
    float c = s;
    float cb = c * (2.0f / (s + 4.0f));
    float p1 = 0.5f * s + 1.0f;
    float p2 = 0.5f * s + 2.0f;
#pragma unroll
    for (int k = 0; k < KK; k++) {
        float d = fabsf(ctr - ((float)(s0 + k) + 0.5f));
        float v;
        if (d < p1)      v = c * (1.0f - a * d * d);
        else if (d < p2) { float t = d - p2; v = cb * t * t; }
        else             v = 0.0f;
        p[k] = v;
    }
}

// y flavor: 8 padded lanes from aligned ybase, masked to [sy0, sy0+5)
__device__ __forceinline__ void pot_y8(float coord, float s, int sy0, int ybase, float* p) {
    float ctr = coord + 0.5f * s;
    float a = 4.0f / ((s + 2.0f) * (s + 4.0f));
    float c = s;
    float cb = c * (2.0f / (s + 4.0f));
    float p1 = 0.5f * s + 1.0f;
    float p2 = 0.5f * s + 2.0f;
#pragma unroll
    for (int j = 0; j < 8; j++) {
        int g = ybase + j;
        float d = fabsf(ctr - ((float)g + 0.5f));
        float v;
        if (d < p1)      v = c * (1.0f - a * d * d);
        else if (d < p2) { float t = d - p2; v = cb * t * t; }
        else             v = 0.0f;
        bool in = (g >= sy0) && (g < sy0 + KK);
        p[j] = in ? v : 0.0f;
    }
}

// ---------------------------------------------------------------------------
// Kernel 1: init map (float4), counters, output scalar
// ---------------------------------------------------------------------------
__global__ void __launch_bounds__(256) init_kernel(const float4* __restrict__ initial,
                                                   float* __restrict__ out) {
    int i = blockIdx.x * blockDim.x + threadIdx.x;   // 65536 threads
    if (i < NC / 4) {
        ((float4*)g_density)[i] = initial[i];
        ((int4*)g_cnt)[i] = make_int4(0, 0, 0, 0);
    }
    if (i == 0) { out[0] = 0.0f; g_ovf_cnt = 0; }
}

// ---------------------------------------------------------------------------
// Kernel 2: bucket nodes by UNCLAMPED cell key (uniform load, no pileup)
// ---------------------------------------------------------------------------
__global__ void __launch_bounds__(256) bucket_kernel(
    const float* __restrict__ pos,
    const float* __restrict__ sxs,
    const float* __restrict__ sys,
    int n)
{
    int i = blockIdx.x * blockDim.x + threadIdx.x;
    if (i >= n) return;
    float x  = pos[i];
    float y  = pos[n + i];
    float sx = sxs[i];
    float sy = sys[i];

    // unclamped keys: floor(x-2) in [-2, 508] -> +2 -> [0, 510]
    int kx = (int)floorf(x - 2.0f) + 2;
    int ky = (int)floorf(y - 2.0f) + 2;
    int c = (kx << 9) + ky;            // stride 512

    int slot = atomicAdd(&g_cnt[c], 1);
    float4 r = make_float4(x, y, sx, sy);
    if (slot < CAP) {
        g_rec[slot * NC + c] = r;
    } else {
        int o = atomicAdd(&g_ovf_cnt, 1);
        if (o < OVF_CAP) g_ovf[o] = r;
    }
}

// ---------------------------------------------------------------------------
// Kernel 3: one thread per bucket — merge stamps in registers, deposit once.
// Also handles (normally empty) overflow list at the end.
// ---------------------------------------------------------------------------
__global__ void __launch_bounds__(256) merge_kernel() {
    int c = blockIdx.x * blockDim.x + threadIdx.x;
    if (c < NC) {
        int cnt = min(g_cnt[c], CAP);
        if (cnt > 0) {
            int kx = c >> 9;
            int ky = c & 511;
            int sx0 = min(max(kx - 2, 0), NBX - KK);
            int sy0 = min(max(ky - 2, 0), NBY - KK);
            int ybase = sy0 & ~3;

            float st[KK][8];
#pragma unroll
            for (int a = 0; a < KK; a++)
#pragma unroll
                for (int j = 0; j < 8; j++) st[a][j] = 0.0f;

            for (int s = 0; s < cnt; s++) {
                float4 r = g_rec[s * NC + c];
                float px[KK], py[8];
                pot_x5(r.x, r.z, sx0, px);
                pot_y8(r.y, r.w, sy0, ybase, py);
#pragma unroll
                for (int a = 0; a < KK; a++) {
                    float vx = px[a];
#pragma unroll
                    for (int j = 0; j < 8; j++) st[a][j] += vx * py[j];
                }
            }

            float* base = &g_density[sx0 * NBY + ybase];
#pragma unroll
            for (int a = 0; a < KK; a++) {
                float* b = base + a * NBY;
                if (st[a][0] != 0.0f || st[a][1] != 0.0f || st[a][2] != 0.0f || st[a][3] != 0.0f)
                    red_add_v4(b, st[a][0], st[a][1], st[a][2], st[a][3]);
                if (st[a][4] != 0.0f || st[a][5] != 0.0f || st[a][6] != 0.0f || st[a][7] != 0.0f)
                    red_add_v4(b + 4, st[a][4], st[a][5], st[a][6], st[a][7]);
            }
        }
    }

    // ---- overflow fallback (empty in expectation; REDs commute so any order OK)
    int total = min(g_ovf_cnt, OVF_CAP);
    if (total > 0) {
        int gs = gridDim.x * blockDim.x;
        for (int i = blockIdx.x * blockDim.x + threadIdx.x; i < total; i += gs) {
            float4 r = g_ovf[i];
            int sx0 = min(max((int)floorf(r.x - 2.0f), 0), NBX - KK);
            int sy0 = min(max((int)floorf(r.y - 2.0f), 0), NBY - KK);
            int ybase = sy0 & ~3;
            float px[KK], py[8];
            pot_x5(r.x, r.z, sx0, px);
            pot_y8(r.y, r.w, sy0, ybase, py);
            float* base = &g_density[sx0 * NBY + ybase];
#pragma unroll
            for (int a = 0; a < KK; a++) {
                float vx = px[a];
                if (vx != 0.0f) {
                    float* b = base + a * NBY;
                    red_add_v4(b,     vx * py[0], vx * py[1], vx * py[2], vx * py[3]);
                    red_add_v4(b + 4, vx * py[4], vx * py[5], vx * py[6], vx * py[7]);
                }
            }
        }
    }
}

// ---------------------------------------------------------------------------
// Kernel 4: cost = sum((density - target)^2)
// ---------------------------------------------------------------------------
__global__ void __launch_bounds__(256) reduce_kernel(float* __restrict__ out) {
    __shared__ float sdata[8];
    int tid = threadIdx.x;
    float acc = 0.0f;
    for (int i = blockIdx.x * blockDim.x + tid; i < NC;
         i += gridDim.x * blockDim.x) {
        float d = g_density[i] - TARGET_AREA;
        acc += d * d;
    }
#pragma unroll
    for (int off = 16; off > 0; off >>= 1)
        acc += __shfl_xor_sync(0xFFFFFFFF, acc, off);
    if ((tid & 31) == 0) sdata[tid >> 5] = acc;
    __syncthreads();
    if (tid < 8) {
        float v = sdata[tid];
#pragma unroll
        for (int off = 4; off > 0; off >>= 1)
            v += __shfl_xor_sync(0xFF, v, off);
        if (tid == 0) atomicAdd(out, v);
    }
}

// ---------------------------------------------------------------------------
extern "C" void kernel_launch(void* const* d_in, const int* in_sizes, int n_in,
                              void* d_out, int out_size) {
    const float* pos = (const float*)d_in[0];
    const float* sx  = (const float*)d_in[1];
    const float* sy  = (const float*)d_in[2];
    // d_in[3..8]: ax,bx,cx,ay,by,cy — recomputed analytically from sx/sy
    // d_in[9], d_in[10]: bin centers — analytic
    const float* initial = (const float*)d_in[11];
    float* out = (float*)d_out;

    int n = in_sizes[1];

    init_kernel<<<(NC / 4 + 255) / 256, 256>>>((const float4*)initial, out);
    bucket_kernel<<<(n + 255) / 256, 256>>>(pos, sx, sy, n);
    merge_kernel<<<(NC + 255) / 256, 256>>>();
    reduce_kernel<<<256, 256>>>(out);
}